// round 11
// baseline (speedup 1.0000x reference)
#include <cuda_runtime.h>
#include <cuda_bf16.h>
#include <stdint.h>
#include <math.h>

#define NN 4096
#define DD 256
#define HH 4
#define HD 1024   // H*DH row stride of q/k/v
#define OUTD 128

// ---------------- scratch (static device memory; no allocs) ----------------
__device__ float g_t1[NN * DD];
__device__ float g_t2[NN * DD];
__device__ float g_h [NN * DD];
__device__ __nv_bfloat16 g_qb[NN * HD];
__device__ __nv_bfloat16 g_kb[NN * HD];
__device__ __nv_bfloat16 g_vb[NN * HD];
__device__ float g_o [NN * HD];

// pre-split weights (tf32 hi/lo), total 1,081,344 floats each
#define OFF_WIN   0
#define OFF_WM1   65536
#define OFF_WSKIP 131072
#define OFF_WM2   196608
#define OFF_WMEAN 262144
#define OFF_WQ    294912
#define OFF_WK    557056
#define OFF_WV    819200
#define WTOTAL    1081344
__device__ float g_bhi[WTOTAL];
__device__ float g_blo[WTOTAL];

// ---------------- cp.async helpers ----------------
#define CP_ASYNC16(dst32, srcp)                                             \
    asm volatile("cp.async.ca.shared.global [%0], [%1], 16;\n" ::           \
                 "r"(dst32), "l"(srcp))
#define CP_COMMIT()  asm volatile("cp.async.commit_group;\n" ::)
#define CP_WAIT0()   asm volatile("cp.async.wait_group 0;\n" ::)

__device__ __forceinline__ uint32_t smaddr(const void* p) {
    return (uint32_t)__cvta_generic_to_shared(p);
}

__device__ __forceinline__ uint32_t f2tf32(float f) {
    uint32_t r;
    asm("cvt.rna.tf32.f32 %0, %1;" : "=r"(r) : "f"(f));
    return r;
}

__device__ __forceinline__ void split_tf32(float f, uint32_t& hi, uint32_t& lo) {
    hi = f2tf32(f);
    lo = f2tf32(f - __uint_as_float(hi));
}

// ---------------- weight split kernel ----------------
struct SplitArgs {
    const float* src[8];
    int off[8];
    int n[8];
};

__global__ __launch_bounds__(256) void wsplit_kernel(SplitArgs a,
                                                     float* __restrict__ hi,
                                                     float* __restrict__ lo)
{
    const int seg = blockIdx.y;
    const int n = a.n[seg];
    const float* s = a.src[seg];
    float* h = hi + a.off[seg];
    float* l = lo + a.off[seg];
    for (int i = (blockIdx.x * 256 + threadIdx.x) * 4; i < n; i += 64 * 256 * 4) {
        float4 v = *(const float4*)(s + i);
        float4 vh, vl;
        uint32_t th, tl;
        split_tf32(v.x, th, tl); vh.x = __uint_as_float(th); vl.x = __uint_as_float(tl);
        split_tf32(v.y, th, tl); vh.y = __uint_as_float(th); vl.y = __uint_as_float(tl);
        split_tf32(v.z, th, tl); vh.z = __uint_as_float(th); vl.z = __uint_as_float(tl);
        split_tf32(v.w, th, tl); vh.w = __uint_as_float(th); vl.w = __uint_as_float(tl);
        *(float4*)(h + i) = vh;
        *(float4*)(l + i) = vl;
    }
}

// ===================== 3xTF32 split tensor-core GEMM =====================
// C[M,N] = act( A[M,K] @ B[K,N] + bias + residual ), B pre-split into hi/lo tf32.
// act: 0 none, 1 relu, 2 elu ; resmode: 0 none, 1 R MxN, 2 head-mean of R[M,4N]
// obf16: 0 -> C float*, 1 -> C __nv_bfloat16*
// Block 128x64, BK=32, 256 thr = 8 warps (4m x 2n), warp tile 32x32, cp.async dbl-buffered.

__device__ __forceinline__ void mma_tf32(float* d, uint32_t a0, uint32_t a1,
                                         uint32_t a2, uint32_t a3,
                                         uint32_t b0, uint32_t b1) {
    asm volatile(
        "mma.sync.aligned.m16n8k8.row.col.f32.tf32.tf32.f32 "
        "{%0,%1,%2,%3}, {%4,%5,%6,%7}, {%8,%9}, {%0,%1,%2,%3};\n"
        : "+f"(d[0]), "+f"(d[1]), "+f"(d[2]), "+f"(d[3])
        : "r"(a0), "r"(a1), "r"(a2), "r"(a3), "r"(b0), "r"(b1));
}

__global__ __launch_bounds__(256) void gemm_kernel(
    const float* __restrict__ A, const float* __restrict__ Bhi,
    const float* __restrict__ Blo,
    const float* __restrict__ bias, const float* __restrict__ R,
    void* __restrict__ Cout, int M, int N, int K, int act, int resmode, int obf16)
{
    __shared__ float As[2][128][36];   // [m][k], stride 36 -> frag banks 4r+q
    __shared__ float Bh[2][32][72];    // [k][n], stride 72 -> frag banks 8q+r
    __shared__ float Bl[2][32][72];

    const int t    = threadIdx.x;
    const int lane = t & 31;
    const int wid  = t >> 5;
    const int wm   = wid & 3;
    const int wn   = wid >> 2;
    const int bm   = blockIdx.y << 7;
    const int bn   = blockIdx.x << 6;
    const int r    = lane >> 2;        // 0..7
    const int q    = lane & 3;         // 0..3

    float acc[2][4][4];
#pragma unroll
    for (int a = 0; a < 2; a++)
#pragma unroll
        for (int b = 0; b < 4; b++)
#pragma unroll
            for (int c = 0; c < 4; c++) acc[a][b][c] = 0.0f;

    auto stage = [&](int k0, int buf) {
#pragma unroll
        for (int i = 0; i < 4; i++) {           // A: 128x32 fp32 = 1024 x16B
            int idx = t + (i << 8);
            int row = idx >> 3, c4 = idx & 7;
            CP_ASYNC16(smaddr(&As[buf][row][c4 << 2]),
                       A + (size_t)(bm + row) * K + k0 + (c4 << 2));
        }
#pragma unroll
        for (int i = 0; i < 2; i++) {           // Bhi/Blo: 32x64 each = 512 x16B
            int idx = t + (i << 8);
            int kr = idx >> 4, n4 = idx & 15;
            size_t goff = (size_t)(k0 + kr) * N + bn + (n4 << 2);
            CP_ASYNC16(smaddr(&Bh[buf][kr][n4 << 2]), Bhi + goff);
            CP_ASYNC16(smaddr(&Bl[buf][kr][n4 << 2]), Blo + goff);
        }
        CP_COMMIT();
    };

    stage(0, 0);
    const int NS = K >> 5;
    for (int ks = 0; ks < NS; ks++) {
        CP_WAIT0();
        __syncthreads();
        if (ks + 1 < NS) stage((ks + 1) << 5, (ks + 1) & 1);
        const int buf = ks & 1;

#pragma unroll
        for (int k8 = 0; k8 < 4; k8++) {
            int kk = k8 << 3;
            uint32_t ah[2][4], al[2][4];
#pragma unroll
            for (int mt = 0; mt < 2; mt++) {
                int rb = (wm << 5) + (mt << 4);
                split_tf32(As[buf][rb + r][kk + q],          ah[mt][0], al[mt][0]);
                split_tf32(As[buf][rb + 8 + r][kk + q],      ah[mt][1], al[mt][1]);
                split_tf32(As[buf][rb + r][kk + q + 4],      ah[mt][2], al[mt][2]);
                split_tf32(As[buf][rb + 8 + r][kk + q + 4],  ah[mt][3], al[mt][3]);
            }
            uint32_t bh_[4][2], bl_[4][2];
#pragma unroll
            for (int nt = 0; nt < 4; nt++) {
                int cb = (wn << 5) + (nt << 3);
                bh_[nt][0] = __float_as_uint(Bh[buf][kk + q][cb + r]);
                bh_[nt][1] = __float_as_uint(Bh[buf][kk + q + 4][cb + r]);
                bl_[nt][0] = __float_as_uint(Bl[buf][kk + q][cb + r]);
                bl_[nt][1] = __float_as_uint(Bl[buf][kk + q + 4][cb + r]);
            }
#pragma unroll
            for (int mt = 0; mt < 2; mt++)
#pragma unroll
                for (int nt = 0; nt < 4; nt++) {
                    mma_tf32(acc[mt][nt], ah[mt][0], ah[mt][1], ah[mt][2], ah[mt][3],
                             bh_[nt][0], bh_[nt][1]);
                    mma_tf32(acc[mt][nt], al[mt][0], al[mt][1], al[mt][2], al[mt][3],
                             bh_[nt][0], bh_[nt][1]);
                    mma_tf32(acc[mt][nt], ah[mt][0], ah[mt][1], ah[mt][2], ah[mt][3],
                             bl_[nt][0], bl_[nt][1]);
                }
        }
    }

    // epilogue
    const int lc2 = q << 1;
#pragma unroll
    for (int mt = 0; mt < 2; mt++) {
#pragma unroll
        for (int nt = 0; nt < 4; nt++) {
            int row0 = bm + (wm << 5) + (mt << 4) + r;
            int col  = bn + (wn << 5) + (nt << 3) + lc2;
#pragma unroll
            for (int half = 0; half < 2; half++) {
                int row = row0 + (half << 3);
                float v0 = acc[mt][nt][half * 2 + 0] + bias[col];
                float v1 = acc[mt][nt][half * 2 + 1] + bias[col + 1];
                if (resmode == 1) {
                    const float* rr = R + (size_t)row * N + col;
                    v0 += rr[0]; v1 += rr[1];
                } else if (resmode == 2) {
                    const float* rr = R + (size_t)row * (4 * N) + col;
                    v0 += 0.25f * (rr[0] + rr[N] + rr[2 * N] + rr[3 * N]);
                    v1 += 0.25f * (rr[1] + rr[1 + N] + rr[1 + 2 * N] + rr[1 + 3 * N]);
                }
                if (act == 1) { v0 = fmaxf(v0, 0.0f); v1 = fmaxf(v1, 0.0f); }
                else if (act == 2) {
                    v0 = (v0 > 0.0f) ? v0 : expm1f(v0);
                    v1 = (v1 > 0.0f) ? v1 : expm1f(v1);
                }
                if (obf16) {
                    __nv_bfloat162 pk = __floats2bfloat162_rn(v0, v1);
                    *(uint32_t*)((__nv_bfloat16*)Cout + (size_t)row * N + col) =
                        *(uint32_t*)&pk;
                } else {
                    *(float2*)((float*)Cout + (size_t)row * N + col) =
                        make_float2(v0, v1);
                }
            }
        }
    }
}

// ---------------- LayerNorm: one row (256) per block ----------------
__global__ __launch_bounds__(256) void ln_kernel(
    const float* __restrict__ X, const float* __restrict__ gw,
    const float* __restrict__ bw, float* __restrict__ Y)
{
    __shared__ float red[256];
    const int row = blockIdx.x;
    const int t = threadIdx.x;
    float v = X[(size_t)row * DD + t];
    red[t] = v;
    __syncthreads();
    for (int s = 128; s > 0; s >>= 1) {
        if (t < s) red[t] += red[t + s];
        __syncthreads();
    }
    float mean = red[0] * (1.0f / DD);
    __syncthreads();
    float d = v - mean;
    red[t] = d * d;
    __syncthreads();
    for (int s = 128; s > 0; s >>= 1) {
        if (t < s) red[t] += red[t + s];
        __syncthreads();
    }
    float var = red[0] * (1.0f / DD);
    Y[(size_t)row * DD + t] = d * rsqrtf(var + 1e-5f) * gw[t] + bw[t];
}

// ===================== flash attention, bf16 mma + ldmatrix + cp.async =====================
// Br=64, Bc=64, DH=256, 512 threads (16 warps, 4m x 4n), one head per blockIdx.y.
// K/V double-buffered via cp.async; V row-major with ldmatrix.trans B-fragments.
// No online max (|s| <= ~10): P = exp(s/16); l accumulated in registers per lane.

#define BR 64
#define BC 64

struct AttnSmem {
    __nv_bfloat16 Qs[BR][264];      // stride 132 words == 4 mod 32 -> LDSM conflict-free
    __nv_bfloat16 Ks[2][BC][264];
    __nv_bfloat16 Vs[2][BC][264];   // row-major [key][dim]
    __nv_bfloat16 Pb[BR][72];       // stride 36 words == 4 mod 32
    float l_part[4][BR];            // per-wn row partials
};

#define LDM_X4(r0, r1, r2, r3, addr)                                        \
    asm volatile("ldmatrix.sync.aligned.m8n8.x4.shared.b16 {%0,%1,%2,%3}, [%4];" \
                 : "=r"(r0), "=r"(r1), "=r"(r2), "=r"(r3) : "r"(addr))
#define LDM_X4_T(r0, r1, r2, r3, addr)                                      \
    asm volatile("ldmatrix.sync.aligned.m8n8.x4.trans.shared.b16 {%0,%1,%2,%3}, [%4];" \
                 : "=r"(r0), "=r"(r1), "=r"(r2), "=r"(r3) : "r"(addr))

__device__ __forceinline__ void mma16816(float* d, uint32_t a0, uint32_t a1,
                                         uint32_t a2, uint32_t a3,
                                         uint32_t b0, uint32_t b1) {
    asm volatile(
        "mma.sync.aligned.m16n8k16.row.col.f32.bf16.bf16.f32 "
        "{%0,%1,%2,%3}, {%4,%5,%6,%7}, {%8,%9}, {%0,%1,%2,%3};\n"
        : "+f"(d[0]), "+f"(d[1]), "+f"(d[2]), "+f"(d[3])
        : "r"(a0), "r"(a1), "r"(a2), "r"(a3), "r"(b0), "r"(b1));
}

__global__ __launch_bounds__(512) void attn_kernel(
    const __nv_bfloat16* __restrict__ Qg, const __nv_bfloat16* __restrict__ Kg,
    const __nv_bfloat16* __restrict__ Vg, float* __restrict__ O)
{
    extern __shared__ char smem_raw[];
    AttnSmem* s = (AttnSmem*)smem_raw;

    const int t    = threadIdx.x;
    const int wid  = t >> 5;
    const int lane = t & 31;
    const int h    = blockIdx.y;
    const int q0   = blockIdx.x * BR;
    const int hoff = h * 256;

    const int r  = lane >> 2;        // 0..7
    const int cq = (lane & 3) << 1;  // 0,2,4,6

    const int wm = wid & 3;          // row group (16 rows)
    const int wn = wid >> 2;         // col group
    const int sm_row = wm << 4;

    // ldmatrix per-lane offsets
    const int g  = lane >> 3, ri = lane & 7;
    const int arow = ri + ((g & 1) << 3);   // A operand (Q/P), non-trans
    const int acol = (g >> 1) << 3;
    const int brow = ri + ((g >> 1) << 3);  // B operand (K), non-trans
    const int bcol = (g & 1) << 3;
    const int vrow = ri + ((g & 1) << 3);   // B operand (V), trans
    const int vcol = (g >> 1) << 3;

    // load Q block (64 x 256 bf16)
    for (int i = t; i < BR * 32; i += 512) {
        int rr = i >> 5, c4 = i & 31;
        *(float4*)&s->Qs[rr][c4 << 3] =
            ((const float4*)(Qg + (size_t)(q0 + rr) * HD + hoff))[c4];
    }

    float oacc[8][4];
#pragma unroll
    for (int a = 0; a < 8; a++)
#pragma unroll
        for (int b = 0; b < 4; b++) oacc[a][b] = 0.0f;
    float lA = 0.0f, lB = 0.0f;    // Σp for rows sm_row+r, sm_row+8+r (this warp's cols)

    auto stage = [&](int kb, int buf) {
#pragma unroll
        for (int i = 0; i < 4; i++) {          // K: 64x256 bf16 = 1024 x16B
            int idx = t + (i << 9);
            int row = idx >> 5, c = idx & 31;
            CP_ASYNC16(smaddr(&s->Ks[buf][row][c << 3]),
                       Kg + (size_t)(kb + row) * HD + hoff + (c << 3));
        }
#pragma unroll
        for (int i = 0; i < 4; i++) {          // V: 64x256
            int idx = t + (i << 9);
            int row = idx >> 5, c = idx & 31;
            CP_ASYNC16(smaddr(&s->Vs[buf][row][c << 3]),
                       Vg + (size_t)(kb + row) * HD + hoff + (c << 3));
        }
        CP_COMMIT();
    };

    stage(0, 0);
    const int NIT = NN / BC;
    for (int ib = 0; ib < NIT; ib++) {
        CP_WAIT0();
        __syncthreads();                       // K/V[cur] ready; prev iter fully consumed
        if (ib + 1 < NIT) stage((ib + 1) * BC, (ib + 1) & 1);
        const int cur = ib & 1;

        // ---- S = Q @ K^T : warp tile rows [sm_row,+16), cols [wn*16,+16)
        {
            const int sn = wn << 4;
            float sacc[2][4] = {};
#pragma unroll 4
            for (int k0 = 0; k0 < 256; k0 += 16) {
                uint32_t a0, a1, a2, a3, b0, b1, b2, b3;
                LDM_X4(a0, a1, a2, a3, smaddr(&s->Qs[sm_row + arow][k0 + acol]));
                LDM_X4(b0, b1, b2, b3, smaddr(&s->Ks[cur][sn + brow][k0 + bcol]));
                mma16816(sacc[0], a0, a1, a2, a3, b0, b1);
                mma16816(sacc[1], a0, a1, a2, a3, b2, b3);
            }
            const float sc = 0.0625f;   // 1/sqrt(256)
#pragma unroll
            for (int nt = 0; nt < 2; nt++) {
                int col = sn + (nt << 3) + cq;
                float p0 = __expf(sacc[nt][0] * sc);
                float p1 = __expf(sacc[nt][1] * sc);
                float p2 = __expf(sacc[nt][2] * sc);
                float p3 = __expf(sacc[nt][3] * sc);
                lA += p0 + p1;
                lB += p2 + p3;
                __nv_bfloat162 pa = __floats2bfloat162_rn(p0, p1);
                __nv_bfloat162 pb = __floats2bfloat162_rn(p2, p3);
                *(uint32_t*)&s->Pb[sm_row + r][col]     = *(uint32_t*)&pa;
                *(uint32_t*)&s->Pb[sm_row + 8 + r][col] = *(uint32_t*)&pb;
            }
        }
        // only the 4 warps sharing this row group exchange P
        asm volatile("bar.sync %0, %1;" :: "r"(wm + 1), "r"(128) : "memory");

        // ---- O += P @ V : warp tile rows [sm_row,+16), dims [wn*64,+64)
        {
            const int dn = wn << 6;
#pragma unroll
            for (int k0 = 0; k0 < BC; k0 += 16) {
                uint32_t p0, p1, p2, p3;
                LDM_X4(p0, p1, p2, p3, smaddr(&s->Pb[sm_row + arow][k0 + acol]));
#pragma unroll
                for (int nt2 = 0; nt2 < 4; nt2++) {
                    uint32_t v0, v1, v2, v3;
                    LDM_X4_T(v0, v1, v2, v3,
                             smaddr(&s->Vs[cur][k0 + vrow][dn + (nt2 << 4) + vcol]));
                    mma16816(oacc[nt2 * 2],     p0, p1, p2, p3, v0, v1);
                    mma16816(oacc[nt2 * 2 + 1], p0, p1, p2, p3, v2, v3);
                }
            }
        }
    }

    // ---- reduce l: over quad lanes, then over wn groups via smem
    lA += __shfl_xor_sync(0xffffffffu, lA, 1);
    lA += __shfl_xor_sync(0xffffffffu, lA, 2);
    lB += __shfl_xor_sync(0xffffffffu, lB, 1);
    lB += __shfl_xor_sync(0xffffffffu, lB, 2);
    if ((lane & 3) == 0) {
        s->l_part[wn][sm_row + r] = lA;
        s->l_part[wn][sm_row + 8 + r] = lB;
    }
    __syncthreads();

    // ---- epilogue: O / l, write fp32
    {
        const int dn = wn << 6;
        int rowA = sm_row + r, rowB = sm_row + 8 + r;
        float la = s->l_part[0][rowA] + s->l_part[1][rowA] +
                   s->l_part[2][rowA] + s->l_part[3][rowA];
        float lb = s->l_part[0][rowB] + s->l_part[1][rowB] +
                   s->l_part[2][rowB] + s->l_part[3][rowB];
        float ia = 1.0f / la;
        float ib2 = 1.0f / lb;
#pragma unroll
        for (int nt = 0; nt < 8; nt++) {
            int col = dn + (nt << 3) + cq;
            float2 va = make_float2(oacc[nt][0] * ia,  oacc[nt][1] * ia);
            float2 vb = make_float2(oacc[nt][2] * ib2, oacc[nt][3] * ib2);
            *(float2*)&O[(size_t)(q0 + rowA) * HD + hoff + col] = va;
            *(float2*)&O[(size_t)(q0 + rowB) * HD + hoff + col] = vb;
        }
    }
}

// ---------------- launch ----------------
extern "C" void kernel_launch(void* const* d_in, const int* in_sizes, int n_in,
                              void* d_out, int out_size)
{
    const float* x     = (const float*)d_in[0];
    const float* w_in  = (const float*)d_in[1];
    const float* b_in  = (const float*)d_in[2];
    const float* w_m1  = (const float*)d_in[3];
    const float* b_m1  = (const float*)d_in[4];
    const float* gm1   = (const float*)d_in[5];
    const float* bem1  = (const float*)d_in[6];
    const float* wq    = (const float*)d_in[7];
    const float* bq    = (const float*)d_in[8];
    const float* wk    = (const float*)d_in[9];
    const float* bk    = (const float*)d_in[10];
    const float* wv    = (const float*)d_in[11];
    const float* bv    = (const float*)d_in[12];
    const float* wskip = (const float*)d_in[13];
    const float* bskip = (const float*)d_in[14];
    const float* gn1   = (const float*)d_in[15];
    const float* ben1  = (const float*)d_in[16];
    const float* w_m2  = (const float*)d_in[17];
    const float* b_m2  = (const float*)d_in[18];
    const float* gm2   = (const float*)d_in[19];
    const float* bem2  = (const float*)d_in[20];
    const float* w_mean = (const float*)d_in[21];
    const float* b_mean = (const float*)d_in[22];
    float* out = (float*)d_out;

    float *t1, *t2, *h, *o, *bhi, *blo;
    __nv_bfloat16 *qb, *kb, *vb;
    cudaGetSymbolAddress((void**)&t1, g_t1);
    cudaGetSymbolAddress((void**)&t2, g_t2);
    cudaGetSymbolAddress((void**)&h,  g_h);
    cudaGetSymbolAddress((void**)&qb, g_qb);
    cudaGetSymbolAddress((void**)&kb, g_kb);
    cudaGetSymbolAddress((void**)&vb, g_vb);
    cudaGetSymbolAddress((void**)&o,  g_o);
    cudaGetSymbolAddress((void**)&bhi, g_bhi);
    cudaGetSymbolAddress((void**)&blo, g_blo);

    const int ATTN_SMEM = (int)sizeof(AttnSmem);
    cudaFuncSetAttribute(attn_kernel, cudaFuncAttributeMaxDynamicSharedMemorySize,
                         ATTN_SMEM);

    // split weights into tf32 hi/lo
    SplitArgs sa;
    sa.src[0] = w_in;   sa.off[0] = OFF_WIN;   sa.n[0] = DD * DD;
    sa.src[1] = w_m1;   sa.off[1] = OFF_WM1;   sa.n[1] = DD * DD;
    sa.src[2] = wskip;  sa.off[2] = OFF_WSKIP; sa.n[2] = DD * DD;
    sa.src[3] = w_m2;   sa.off[3] = OFF_WM2;   sa.n[3] = DD * DD;
    sa.src[4] = w_mean; sa.off[4] = OFF_WMEAN; sa.n[4] = DD * OUTD;
    sa.src[5] = wq;     sa.off[5] = OFF_WQ;    sa.n[5] = DD * HD;
    sa.src[6] = wk;     sa.off[6] = OFF_WK;    sa.n[6] = DD * HD;
    sa.src[7] = wv;     sa.off[7] = OFF_WV;    sa.n[7] = DD * HD;
    wsplit_kernel<<<dim3(64, 8), 256>>>(sa, bhi, blo);

    dim3 blk(256);
    dim3 gD(DD / 64, NN / 128);
    dim3 gH(HD / 64, NN / 128);
    dim3 gO(OUTD / 64, NN / 128);

    // input_layer: t1 = elu(x @ w_in + b_in + x)
    gemm_kernel<<<gD, blk>>>(x, bhi + OFF_WIN, blo + OFF_WIN, b_in, x, t1,
                             NN, DD, DD, 2, 1, 0);
    // mlp1 pre-LN: t2 = relu(t1 @ w_m1 + b_m1 + t1)
    gemm_kernel<<<gD, blk>>>(t1, bhi + OFF_WM1, blo + OFF_WM1, b_m1, t1, t2,
                             NN, DD, DD, 1, 1, 0);
    ln_kernel<<<NN, blk>>>(t2, gm1, bem1, h);
    // QKV -> bf16
    gemm_kernel<<<gH, blk>>>(h, bhi + OFF_WQ, blo + OFF_WQ, bq, nullptr, qb,
                             NN, HD, DD, 0, 0, 1);
    gemm_kernel<<<gH, blk>>>(h, bhi + OFF_WK, blo + OFF_WK, bk, nullptr, kb,
                             NN, HD, DD, 0, 0, 1);
    gemm_kernel<<<gH, blk>>>(h, bhi + OFF_WV, blo + OFF_WV, bv, nullptr, vb,
                             NN, HD, DD, 0, 0, 1);
    // attention (tensor cores + ldmatrix + cp.async pipeline)
    attn_kernel<<<dim3(NN / BR, HH), dim3(512), ATTN_SMEM>>>(qb, kb, vb, o);
    // skip: t1 = head_mean(O) + h @ wskip + bskip
    gemm_kernel<<<gD, blk>>>(h, bhi + OFF_WSKIP, blo + OFF_WSKIP, bskip, o, t1,
                             NN, DD, DD, 0, 2, 0);
    ln_kernel<<<NN, blk>>>(t1, gn1, ben1, t2);
    // mlp2: t1 = relu(t2 @ w_m2 + b_m2 + t2) ; h = LN(t1)
    gemm_kernel<<<gD, blk>>>(t2, bhi + OFF_WM2, blo + OFF_WM2, b_m2, t2, t1,
                             NN, DD, DD, 1, 1, 0);
    ln_kernel<<<NN, blk>>>(t1, gm2, bem2, h);
    // output head
    gemm_kernel<<<gO, blk>>>(h, bhi + OFF_WMEAN, blo + OFF_WMEAN, b_mean, nullptr, out,
                             NN, OUTD, DD, 0, 0, 0);
}

// round 12
// speedup vs baseline: 1.7511x; 1.7511x over previous
#include <cuda_runtime.h>
#include <cuda_bf16.h>
#include <stdint.h>
#include <math.h>

#define NN 4096
#define DD 256
#define HH 4
#define HD 1024   // H*DH row stride of q/k/v
#define OUTD 128

// ---------------- scratch (static device memory; no allocs) ----------------
__device__ float g_t1[NN * DD];
__device__ float g_t2[NN * DD];
__device__ float g_h [NN * DD];
__device__ __nv_bfloat16 g_qb[NN * HD];
__device__ __nv_bfloat16 g_kb[NN * HD];
__device__ __nv_bfloat16 g_vb[NN * HD];
__device__ float g_o [NN * HD];

// ---------------- cp.async helpers ----------------
#define CP_ASYNC16(dst32, srcp)                                             \
    asm volatile("cp.async.ca.shared.global [%0], [%1], 16;\n" ::           \
                 "r"(dst32), "l"(srcp))
#define CP_COMMIT()  asm volatile("cp.async.commit_group;\n" ::)
#define CP_WAIT0()   asm volatile("cp.async.wait_group 0;\n" ::)

__device__ __forceinline__ uint32_t smaddr(const void* p) {
    return (uint32_t)__cvta_generic_to_shared(p);
}

// ===================== 3xTF32 split tensor-core GEMM (round-9 proven) =====================
// C[M,N] = act( A[M,K] @ B[K,N] + bias + residual )
// act: 0 none, 1 relu, 2 elu ; resmode: 0 none, 1 R MxN, 2 head-mean of R[M,4N]
// obf16: 0 -> C float*, 1 -> C __nv_bfloat16*
// Block 128x64, BK=32, 256 thr = 8 warps (4m x 2n), warp tile 32x32, cp.async dbl-buffered.

__device__ __forceinline__ uint32_t f2tf32(float f) {
    uint32_t r;
    asm("cvt.rna.tf32.f32 %0, %1;" : "=r"(r) : "f"(f));
    return r;
}

__device__ __forceinline__ void split_tf32(float f, uint32_t& hi, uint32_t& lo) {
    hi = f2tf32(f);
    lo = f2tf32(f - __uint_as_float(hi));
}

__device__ __forceinline__ void mma_tf32(float* d, uint32_t a0, uint32_t a1,
                                         uint32_t a2, uint32_t a3,
                                         uint32_t b0, uint32_t b1) {
    asm volatile(
        "mma.sync.aligned.m16n8k8.row.col.f32.tf32.tf32.f32 "
        "{%0,%1,%2,%3}, {%4,%5,%6,%7}, {%8,%9}, {%0,%1,%2,%3};\n"
        : "+f"(d[0]), "+f"(d[1]), "+f"(d[2]), "+f"(d[3])
        : "r"(a0), "r"(a1), "r"(a2), "r"(a3), "r"(b0), "r"(b1));
}

__global__ __launch_bounds__(256) void gemm_kernel(
    const float* __restrict__ A, const float* __restrict__ B,
    const float* __restrict__ bias, const float* __restrict__ R,
    void* __restrict__ Cout, int M, int N, int K, int act, int resmode, int obf16)
{
    __shared__ float As[2][128][36];   // [m][k], stride 36 -> frag banks 4r+q
    __shared__ float Bs[2][32][72];    // [k][n], stride 72 -> frag banks 8q+r

    const int t    = threadIdx.x;
    const int lane = t & 31;
    const int wid  = t >> 5;
    const int wm   = wid & 3;
    const int wn   = wid >> 2;
    const int bm   = blockIdx.y << 7;
    const int bn   = blockIdx.x << 6;
    const int r    = lane >> 2;        // 0..7
    const int q    = lane & 3;         // 0..3

    float acc[2][4][4];
#pragma unroll
    for (int a = 0; a < 2; a++)
#pragma unroll
        for (int b = 0; b < 4; b++)
#pragma unroll
            for (int c = 0; c < 4; c++) acc[a][b][c] = 0.0f;

    auto stage = [&](int k0, int buf) {
#pragma unroll
        for (int i = 0; i < 4; i++) {           // A: 128x32 fp32 = 1024 x16B
            int idx = t + (i << 8);
            int row = idx >> 3, c4 = idx & 7;
            CP_ASYNC16(smaddr(&As[buf][row][c4 << 2]),
                       A + (size_t)(bm + row) * K + k0 + (c4 << 2));
        }
#pragma unroll
        for (int i = 0; i < 2; i++) {           // B: 32x64 fp32 = 512 x16B
            int idx = t + (i << 8);
            int kr = idx >> 4, n4 = idx & 15;
            CP_ASYNC16(smaddr(&Bs[buf][kr][n4 << 2]),
                       B + (size_t)(k0 + kr) * N + bn + (n4 << 2));
        }
        CP_COMMIT();
    };

    stage(0, 0);
    const int NS = K >> 5;
    for (int ks = 0; ks < NS; ks++) {
        CP_WAIT0();
        __syncthreads();
        if (ks + 1 < NS) stage((ks + 1) << 5, (ks + 1) & 1);
        const int buf = ks & 1;

#pragma unroll
        for (int k8 = 0; k8 < 4; k8++) {
            int kk = k8 << 3;
            uint32_t ah[2][4], al[2][4];
#pragma unroll
            for (int mt = 0; mt < 2; mt++) {
                int rb = (wm << 5) + (mt << 4);
                split_tf32(As[buf][rb + r][kk + q],          ah[mt][0], al[mt][0]);
                split_tf32(As[buf][rb + 8 + r][kk + q],      ah[mt][1], al[mt][1]);
                split_tf32(As[buf][rb + r][kk + q + 4],      ah[mt][2], al[mt][2]);
                split_tf32(As[buf][rb + 8 + r][kk + q + 4],  ah[mt][3], al[mt][3]);
            }
            uint32_t bh[4][2], bl[4][2];
#pragma unroll
            for (int nt = 0; nt < 4; nt++) {
                int cb = (wn << 5) + (nt << 3);
                split_tf32(Bs[buf][kk + q][cb + r],      bh[nt][0], bl[nt][0]);
                split_tf32(Bs[buf][kk + q + 4][cb + r],  bh[nt][1], bl[nt][1]);
            }
#pragma unroll
            for (int mt = 0; mt < 2; mt++)
#pragma unroll
                for (int nt = 0; nt < 4; nt++) {
                    mma_tf32(acc[mt][nt], ah[mt][0], ah[mt][1], ah[mt][2], ah[mt][3],
                             bh[nt][0], bh[nt][1]);
                    mma_tf32(acc[mt][nt], al[mt][0], al[mt][1], al[mt][2], al[mt][3],
                             bh[nt][0], bh[nt][1]);
                    mma_tf32(acc[mt][nt], ah[mt][0], ah[mt][1], ah[mt][2], ah[mt][3],
                             bl[nt][0], bl[nt][1]);
                }
        }
    }

    // epilogue
    const int lc2 = q << 1;
#pragma unroll
    for (int mt = 0; mt < 2; mt++) {
#pragma unroll
        for (int nt = 0; nt < 4; nt++) {
            int row0 = bm + (wm << 5) + (mt << 4) + r;
            int col  = bn + (wn << 5) + (nt << 3) + lc2;
#pragma unroll
            for (int half = 0; half < 2; half++) {
                int row = row0 + (half << 3);
                float v0 = acc[mt][nt][half * 2 + 0] + bias[col];
                float v1 = acc[mt][nt][half * 2 + 1] + bias[col + 1];
                if (resmode == 1) {
                    const float* rr = R + (size_t)row * N + col;
                    v0 += rr[0]; v1 += rr[1];
                } else if (resmode == 2) {
                    const float* rr = R + (size_t)row * (4 * N) + col;
                    v0 += 0.25f * (rr[0] + rr[N] + rr[2 * N] + rr[3 * N]);
                    v1 += 0.25f * (rr[1] + rr[1 + N] + rr[1 + 2 * N] + rr[1 + 3 * N]);
                }
                if (act == 1) { v0 = fmaxf(v0, 0.0f); v1 = fmaxf(v1, 0.0f); }
                else if (act == 2) {
                    v0 = (v0 > 0.0f) ? v0 : expm1f(v0);
                    v1 = (v1 > 0.0f) ? v1 : expm1f(v1);
                }
                if (obf16) {
                    __nv_bfloat162 pk = __floats2bfloat162_rn(v0, v1);
                    *(uint32_t*)((__nv_bfloat16*)Cout + (size_t)row * N + col) =
                        *(uint32_t*)&pk;
                } else {
                    *(float2*)((float*)Cout + (size_t)row * N + col) =
                        make_float2(v0, v1);
                }
            }
        }
    }
}

// ---------------- LayerNorm: warp per row, 8 rows/block, no block syncs ----------------
__global__ __launch_bounds__(256) void ln_kernel(
    const float* __restrict__ X, const float* __restrict__ gw,
    const float* __restrict__ bw, float* __restrict__ Y)
{
    const int row  = (blockIdx.x << 3) + (threadIdx.x >> 5);
    const int lane = threadIdx.x & 31;
    const float4* xr = (const float4*)(X + (size_t)row * DD);
    float4 a = xr[lane];
    float4 b = xr[lane + 32];
    float sum = a.x + a.y + a.z + a.w + b.x + b.y + b.z + b.w;
#pragma unroll
    for (int o = 16; o > 0; o >>= 1)
        sum += __shfl_xor_sync(0xffffffffu, sum, o);
    float mean = sum * (1.0f / DD);
    float dax = a.x - mean, day = a.y - mean, daz = a.z - mean, daw = a.w - mean;
    float dbx = b.x - mean, dby = b.y - mean, dbz = b.z - mean, dbw = b.w - mean;
    float vs = dax * dax + day * day + daz * daz + daw * daw +
               dbx * dbx + dby * dby + dbz * dbz + dbw * dbw;
#pragma unroll
    for (int o = 16; o > 0; o >>= 1)
        vs += __shfl_xor_sync(0xffffffffu, vs, o);
    float inv = rsqrtf(vs * (1.0f / DD) + 1e-5f);
    float4 g0 = ((const float4*)gw)[lane];
    float4 g1 = ((const float4*)gw)[lane + 32];
    float4 b0 = ((const float4*)bw)[lane];
    float4 b1 = ((const float4*)bw)[lane + 32];
    float4 o0 = make_float4(dax * inv * g0.x + b0.x, day * inv * g0.y + b0.y,
                            daz * inv * g0.z + b0.z, daw * inv * g0.w + b0.w);
    float4 o1 = make_float4(dbx * inv * g1.x + b1.x, dby * inv * g1.y + b1.y,
                            dbz * inv * g1.z + b1.z, dbw * inv * g1.w + b1.w);
    float4* yr = (float4*)(Y + (size_t)row * DD);
    yr[lane] = o0;
    yr[lane + 32] = o1;
}

// ===================== flash attention, bf16 mma + ldmatrix + cp.async =====================
// Br=128, Bc=64, DH=256: grid (32,4) = 128 blocks = ONE wave on 148 SMs.
// 512 threads (16 warps: 8 row-groups x 2 col-groups). K/V double-buffered.
// No online max (|s| <= ~10): P = exp(s/16); l accumulated in registers per lane.

#define BR 128
#define BC 64

struct AttnSmem {
    __nv_bfloat16 Qs[BR][264];      // stride 132 words == 4 mod 32 -> LDSM conflict-free
    __nv_bfloat16 Ks[2][BC][264];
    __nv_bfloat16 Vs[2][BC][264];   // row-major [key][dim]
    __nv_bfloat16 Pb[BR][72];       // stride 36 words == 4 mod 32
    float l_part[2][BR];            // per-wn row partials
};

#define LDM_X4(r0, r1, r2, r3, addr)                                        \
    asm volatile("ldmatrix.sync.aligned.m8n8.x4.shared.b16 {%0,%1,%2,%3}, [%4];" \
                 : "=r"(r0), "=r"(r1), "=r"(r2), "=r"(r3) : "r"(addr))
#define LDM_X4_T(r0, r1, r2, r3, addr)                                      \
    asm volatile("ldmatrix.sync.aligned.m8n8.x4.trans.shared.b16 {%0,%1,%2,%3}, [%4];" \
                 : "=r"(r0), "=r"(r1), "=r"(r2), "=r"(r3) : "r"(addr))

__device__ __forceinline__ void mma16816(float* d, uint32_t a0, uint32_t a1,
                                         uint32_t a2, uint32_t a3,
                                         uint32_t b0, uint32_t b1) {
    asm volatile(
        "mma.sync.aligned.m16n8k16.row.col.f32.bf16.bf16.f32 "
        "{%0,%1,%2,%3}, {%4,%5,%6,%7}, {%8,%9}, {%0,%1,%2,%3};\n"
        : "+f"(d[0]), "+f"(d[1]), "+f"(d[2]), "+f"(d[3])
        : "r"(a0), "r"(a1), "r"(a2), "r"(a3), "r"(b0), "r"(b1));
}

__global__ __launch_bounds__(512) void attn_kernel(
    const __nv_bfloat16* __restrict__ Qg, const __nv_bfloat16* __restrict__ Kg,
    const __nv_bfloat16* __restrict__ Vg, float* __restrict__ O)
{
    extern __shared__ char smem_raw[];
    AttnSmem* s = (AttnSmem*)smem_raw;

    const int t    = threadIdx.x;
    const int wid  = t >> 5;
    const int lane = t & 31;
    const int h    = blockIdx.y;
    const int q0   = blockIdx.x * BR;
    const int hoff = h * 256;

    const int r  = lane >> 2;        // 0..7
    const int cq = (lane & 3) << 1;  // 0,2,4,6

    const int wm = wid & 7;          // row group (16 rows)
    const int wn = wid >> 3;         // col group (0..1)
    const int sm_row = wm << 4;

    // ldmatrix per-lane offsets
    const int g  = lane >> 3, ri = lane & 7;
    const int arow = ri + ((g & 1) << 3);   // A operand (Q/P), non-trans
    const int acol = (g >> 1) << 3;
    const int brow = ri + ((g >> 1) << 3);  // B operand (K), non-trans
    const int bcol = (g & 1) << 3;
    const int vrow = ri + ((g & 1) << 3);   // B operand (V), trans
    const int vcol = (g >> 1) << 3;

    // load Q block (128 x 256 bf16)
    for (int i = t; i < BR * 32; i += 512) {
        int rr = i >> 5, c4 = i & 31;
        *(float4*)&s->Qs[rr][c4 << 3] =
            ((const float4*)(Qg + (size_t)(q0 + rr) * HD + hoff))[c4];
    }

    float oacc[16][4];
#pragma unroll
    for (int a = 0; a < 16; a++)
#pragma unroll
        for (int b = 0; b < 4; b++) oacc[a][b] = 0.0f;
    float lA = 0.0f, lB = 0.0f;    // Σp for rows sm_row+r, sm_row+8+r (this warp's cols)

    auto stage = [&](int kb, int buf) {
#pragma unroll
        for (int i = 0; i < 4; i++) {          // K: 64x256 bf16 = 2048 x16B
            int idx = t + (i << 9);
            int row = idx >> 5, c = idx & 31;
            CP_ASYNC16(smaddr(&s->Ks[buf][row][c << 3]),
                       Kg + (size_t)(kb + row) * HD + hoff + (c << 3));
        }
#pragma unroll
        for (int i = 0; i < 4; i++) {          // V: 64x256
            int idx = t + (i << 9);
            int row = idx >> 5, c = idx & 31;
            CP_ASYNC16(smaddr(&s->Vs[buf][row][c << 3]),
                       Vg + (size_t)(kb + row) * HD + hoff + (c << 3));
        }
        CP_COMMIT();
    };

    stage(0, 0);
    const int NIT = NN / BC;
    for (int ib = 0; ib < NIT; ib++) {
        CP_WAIT0();
        __syncthreads();                       // K/V[cur] ready; prev iter fully consumed
        if (ib + 1 < NIT) stage((ib + 1) * BC, (ib + 1) & 1);
        const int cur = ib & 1;

        // ---- S = Q @ K^T : warp tile rows [sm_row,+16), cols [wn*32,+32)
        {
            const int sn = wn << 5;
            float sacc[4][4] = {};
#pragma unroll 4
            for (int k0 = 0; k0 < 256; k0 += 16) {
                uint32_t a0, a1, a2, a3, b0, b1, b2, b3, b4, b5, b6, b7;
                LDM_X4(a0, a1, a2, a3, smaddr(&s->Qs[sm_row + arow][k0 + acol]));
                LDM_X4(b0, b1, b2, b3, smaddr(&s->Ks[cur][sn + brow][k0 + bcol]));
                LDM_X4(b4, b5, b6, b7, smaddr(&s->Ks[cur][sn + 16 + brow][k0 + bcol]));
                mma16816(sacc[0], a0, a1, a2, a3, b0, b1);
                mma16816(sacc[1], a0, a1, a2, a3, b2, b3);
                mma16816(sacc[2], a0, a1, a2, a3, b4, b5);
                mma16816(sacc[3], a0, a1, a2, a3, b6, b7);
            }
            const float sc = 0.0625f;   // 1/sqrt(256)
#pragma unroll
            for (int nt = 0; nt < 4; nt++) {
                int col = sn + (nt << 3) + cq;
                float p0 = __expf(sacc[nt][0] * sc);
                float p1 = __expf(sacc[nt][1] * sc);
                float p2 = __expf(sacc[nt][2] * sc);
                float p3 = __expf(sacc[nt][3] * sc);
                lA += p0 + p1;
                lB += p2 + p3;
                __nv_bfloat162 pa = __floats2bfloat162_rn(p0, p1);
                __nv_bfloat162 pb = __floats2bfloat162_rn(p2, p3);
                *(uint32_t*)&s->Pb[sm_row + r][col]     = *(uint32_t*)&pa;
                *(uint32_t*)&s->Pb[sm_row + 8 + r][col] = *(uint32_t*)&pb;
            }
        }
        __syncthreads();

        // ---- O += P @ V : warp tile rows [sm_row,+16), dims [wn*128,+128)
        {
            const int dn = wn << 7;
#pragma unroll
            for (int k0 = 0; k0 < BC; k0 += 16) {
                uint32_t p0, p1, p2, p3;
                LDM_X4(p0, p1, p2, p3, smaddr(&s->Pb[sm_row + arow][k0 + acol]));
#pragma unroll
                for (int nt2 = 0; nt2 < 8; nt2++) {
                    uint32_t v0, v1, v2, v3;
                    LDM_X4_T(v0, v1, v2, v3,
                             smaddr(&s->Vs[cur][k0 + vrow][dn + (nt2 << 4) + vcol]));
                    mma16816(oacc[nt2 * 2],     p0, p1, p2, p3, v0, v1);
                    mma16816(oacc[nt2 * 2 + 1], p0, p1, p2, p3, v2, v3);
                }
            }
        }
    }

    // ---- reduce l: over quad lanes, then over wn groups via smem
    lA += __shfl_xor_sync(0xffffffffu, lA, 1);
    lA += __shfl_xor_sync(0xffffffffu, lA, 2);
    lB += __shfl_xor_sync(0xffffffffu, lB, 1);
    lB += __shfl_xor_sync(0xffffffffu, lB, 2);
    if ((lane & 3) == 0) {
        s->l_part[wn][sm_row + r] = lA;
        s->l_part[wn][sm_row + 8 + r] = lB;
    }
    __syncthreads();

    // ---- epilogue: O / l, write fp32
    {
        const int dn = wn << 7;
        int rowA = sm_row + r, rowB = sm_row + 8 + r;
        float la = s->l_part[0][rowA] + s->l_part[1][rowA];
        float lb = s->l_part[0][rowB] + s->l_part[1][rowB];
        float ia = 1.0f / la;
        float ib2 = 1.0f / lb;
#pragma unroll
        for (int nt = 0; nt < 16; nt++) {
            int col = dn + (nt << 3) + cq;
            float2 va = make_float2(oacc[nt][0] * ia,  oacc[nt][1] * ia);
            float2 vb = make_float2(oacc[nt][2] * ib2, oacc[nt][3] * ib2);
            *(float2*)&O[(size_t)(q0 + rowA) * HD + hoff + col] = va;
            *(float2*)&O[(size_t)(q0 + rowB) * HD + hoff + col] = vb;
        }
    }
}

// ---------------- launch ----------------
extern "C" void kernel_launch(void* const* d_in, const int* in_sizes, int n_in,
                              void* d_out, int out_size)
{
    const float* x     = (const float*)d_in[0];
    const float* w_in  = (const float*)d_in[1];
    const float* b_in  = (const float*)d_in[2];
    const float* w_m1  = (const float*)d_in[3];
    const float* b_m1  = (const float*)d_in[4];
    const float* gm1   = (const float*)d_in[5];
    const float* bem1  = (const float*)d_in[6];
    const float* wq    = (const float*)d_in[7];
    const float* bq    = (const float*)d_in[8];
    const float* wk    = (const float*)d_in[9];
    const float* bk    = (const float*)d_in[10];
    const float* wv    = (const float*)d_in[11];
    const float* bv    = (const float*)d_in[12];
    const float* wskip = (const float*)d_in[13];
    const float* bskip = (const float*)d_in[14];
    const float* gn1   = (const float*)d_in[15];
    const float* ben1  = (const float*)d_in[16];
    const float* w_m2  = (const float*)d_in[17];
    const float* b_m2  = (const float*)d_in[18];
    const float* gm2   = (const float*)d_in[19];
    const float* bem2  = (const float*)d_in[20];
    const float* w_mean = (const float*)d_in[21];
    const float* b_mean = (const float*)d_in[22];
    float* out = (float*)d_out;

    float *t1, *t2, *h, *o;
    __nv_bfloat16 *qb, *kb, *vb;
    cudaGetSymbolAddress((void**)&t1, g_t1);
    cudaGetSymbolAddress((void**)&t2, g_t2);
    cudaGetSymbolAddress((void**)&h,  g_h);
    cudaGetSymbolAddress((void**)&qb, g_qb);
    cudaGetSymbolAddress((void**)&kb, g_kb);
    cudaGetSymbolAddress((void**)&vb, g_vb);
    cudaGetSymbolAddress((void**)&o,  g_o);

    const int ATTN_SMEM = (int)sizeof(AttnSmem);
    cudaFuncSetAttribute(attn_kernel, cudaFuncAttributeMaxDynamicSharedMemorySize,
                         ATTN_SMEM);

    dim3 blk(256);
    dim3 gD(DD / 64, NN / 128);
    dim3 gH(HD / 64, NN / 128);
    dim3 gO(OUTD / 64, NN / 128);
    dim3 gLN(NN / 8);

    // input_layer: t1 = elu(x @ w_in + b_in + x)
    gemm_kernel<<<gD, blk>>>(x, w_in, b_in, x, t1, NN, DD, DD, 2, 1, 0);
    // mlp1 pre-LN: t2 = relu(t1 @ w_m1 + b_m1 + t1)
    gemm_kernel<<<gD, blk>>>(t1, w_m1, b_m1, t1, t2, NN, DD, DD, 1, 1, 0);
    ln_kernel<<<gLN, blk>>>(t2, gm1, bem1, h);
    // QKV -> bf16
    gemm_kernel<<<gH, blk>>>(h, wq, bq, nullptr, qb, NN, HD, DD, 0, 0, 1);
    gemm_kernel<<<gH, blk>>>(h, wk, bk, nullptr, kb, NN, HD, DD, 0, 0, 1);
    gemm_kernel<<<gH, blk>>>(h, wv, bv, nullptr, vb, NN, HD, DD, 0, 0, 1);
    // attention (tensor cores + ldmatrix + cp.async, 1 wave)
    attn_kernel<<<dim3(NN / BR, HH), dim3(512), ATTN_SMEM>>>(qb, kb, vb, o);
    // skip: t1 = head_mean(O) + h @ wskip + bskip
    gemm_kernel<<<gD, blk>>>(h, wskip, bskip, o, t1, NN, DD, DD, 0, 2, 0);
    ln_kernel<<<gLN, blk>>>(t1, gn1, ben1, t2);
    // mlp2: t1 = relu(t2 @ w_m2 + b_m2 + t2) ; h = LN(t1)
    gemm_kernel<<<gD, blk>>>(t2, w_m2, b_m2, t2, t1, NN, DD, DD, 1, 1, 0);
    ln_kernel<<<gLN, blk>>>(t1, gm2, bem2, h);
    // output head
    gemm_kernel<<<gO, blk>>>(h, w_mean, b_mean, nullptr, out, NN, OUTD, DD, 0, 0, 0);
}

// round 14
// speedup vs baseline: 2.0495x; 1.1704x over previous
#include <cuda_runtime.h>
#include <cuda_bf16.h>
#include <stdint.h>
#include <math.h>

#define NN 4096
#define DD 256
#define HH 4
#define HD 1024   // H*DH row stride of q/k/v
#define OUTD 128

// ---------------- scratch (static device memory; no allocs) ----------------
__device__ float g_t1[NN * DD];
__device__ float g_t2[NN * DD];
__device__ float g_h [NN * DD];
__device__ __nv_bfloat16 g_qb[NN * HD];
__device__ __nv_bfloat16 g_kb[NN * HD];
__device__ __nv_bfloat16 g_vb[NN * HD];
__device__ float g_o [NN * HD];

// bf16 hi/lo activation buffers (ping-pong A operands)
__device__ __nv_bfloat16 g_hiA[NN * DD], g_loA[NN * DD];
__device__ __nv_bfloat16 g_hiB[NN * DD], g_loB[NN * DD];

// pre-split weights (bf16 hi/lo)
#define OFF_WIN   0
#define OFF_WM1   65536
#define OFF_WSKIP 131072
#define OFF_WM2   196608
#define OFF_WMEAN 262144
#define OFF_WQ    294912
#define OFF_WK    557056
#define OFF_WV    819200
#define WTOTAL    1081344
__device__ __nv_bfloat16 g_whi[WTOTAL];
__device__ __nv_bfloat16 g_wlo[WTOTAL];

// ---------------- cp.async helpers ----------------
#define CP_ASYNC16(dst32, srcp)                                             \
    asm volatile("cp.async.ca.shared.global [%0], [%1], 16;\n" ::           \
                 "r"(dst32), "l"(srcp))
#define CP_COMMIT()  asm volatile("cp.async.commit_group;\n" ::)
#define CP_WAIT0()   asm volatile("cp.async.wait_group 0;\n" ::)

__device__ __forceinline__ uint32_t smaddr(const void* p) {
    return (uint32_t)__cvta_generic_to_shared(p);
}

#define LDM_X4(r0, r1, r2, r3, addr)                                        \
    asm volatile("ldmatrix.sync.aligned.m8n8.x4.shared.b16 {%0,%1,%2,%3}, [%4];" \
                 : "=r"(r0), "=r"(r1), "=r"(r2), "=r"(r3) : "r"(addr))
#define LDM_X4_T(r0, r1, r2, r3, addr)                                      \
    asm volatile("ldmatrix.sync.aligned.m8n8.x4.trans.shared.b16 {%0,%1,%2,%3}, [%4];" \
                 : "=r"(r0), "=r"(r1), "=r"(r2), "=r"(r3) : "r"(addr))

__device__ __forceinline__ void mma16816(float* d, uint32_t a0, uint32_t a1,
                                         uint32_t a2, uint32_t a3,
                                         uint32_t b0, uint32_t b1) {
    asm volatile(
        "mma.sync.aligned.m16n8k16.row.col.f32.bf16.bf16.f32 "
        "{%0,%1,%2,%3}, {%4,%5,%6,%7}, {%8,%9}, {%0,%1,%2,%3};\n"
        : "+f"(d[0]), "+f"(d[1]), "+f"(d[2]), "+f"(d[3])
        : "r"(a0), "r"(a1), "r"(a2), "r"(a3), "r"(b0), "r"(b1));
}

__device__ __forceinline__ void bf16split(float v, __nv_bfloat16& hi, __nv_bfloat16& lo) {
    hi = __float2bfloat16(v);
    lo = __float2bfloat16(v - __bfloat162float(hi));
}

// ---------------- weight split kernel (fp32 -> bf16 hi/lo) ----------------
struct SplitArgs {
    const float* src[8];
    int off[8];
    int n[8];
};

__global__ __launch_bounds__(256) void wsplit_kernel(SplitArgs a,
                                                     __nv_bfloat16* __restrict__ hi,
                                                     __nv_bfloat16* __restrict__ lo)
{
    const int seg = blockIdx.y;
    const int n = a.n[seg];
    const float* s = a.src[seg];
    __nv_bfloat16* h = hi + a.off[seg];
    __nv_bfloat16* l = lo + a.off[seg];
    for (int i = (blockIdx.x * 256 + threadIdx.x) * 4; i < n; i += 64 * 256 * 4) {
        float4 v = *(const float4*)(s + i);
        __nv_bfloat16 h0, h1, h2, h3, l0, l1, l2, l3;
        bf16split(v.x, h0, l0); bf16split(v.y, h1, l1);
        bf16split(v.z, h2, l2); bf16split(v.w, h3, l3);
        __nv_bfloat162 ph0 = {h0, h1}, ph1 = {h2, h3};
        __nv_bfloat162 pl0 = {l0, l1}, pl1 = {l2, l3};
        *(__nv_bfloat162*)(h + i)     = ph0;
        *(__nv_bfloat162*)(h + i + 2) = ph1;
        *(__nv_bfloat162*)(l + i)     = pl0;
        *(__nv_bfloat162*)(l + i + 2) = pl1;
    }
}

// ---------------- x split kernel ----------------
__global__ __launch_bounds__(256) void xsplit_kernel(const float* __restrict__ X,
                                                     __nv_bfloat16* __restrict__ hi,
                                                     __nv_bfloat16* __restrict__ lo)
{
    int i = (blockIdx.x * 256 + threadIdx.x) * 4;
    if (i >= NN * DD) return;
    float4 v = *(const float4*)(X + i);
    __nv_bfloat16 h0, h1, h2, h3, l0, l1, l2, l3;
    bf16split(v.x, h0, l0); bf16split(v.y, h1, l1);
    bf16split(v.z, h2, l2); bf16split(v.w, h3, l3);
    __nv_bfloat162 ph0 = {h0, h1}, ph1 = {h2, h3};
    __nv_bfloat162 pl0 = {l0, l1}, pl1 = {l2, l3};
    *(__nv_bfloat162*)(hi + i)     = ph0;
    *(__nv_bfloat162*)(hi + i + 2) = ph1;
    *(__nv_bfloat162*)(lo + i)     = pl0;
    *(__nv_bfloat162*)(lo + i + 2) = pl1;
}

// ===================== 3x bf16-split tensor-core GEMM =====================
// C[M,N] = act( A[M,K] @ B[K,N] + bias + residual ), A and B pre-split bf16 hi/lo.
// acc = Ah@Bh + Al@Bh + Ah@Bl
// act: 0 none, 1 relu, 2 elu ; resmode: 0 none, 1 R MxN, 2 head-mean of R[M,4N]
// omode: 0 -> write fp32 C + bf16 hi/lo (Chi/Clo), 1 -> write single bf16 C
// Block 128x64, BK=64, 256 thr = 8 warps (4m x 2n), warp tile 32x32.
// Row stride 72 bf16 = 144 B (16-aligned for cp.async; 36 words == 4 mod 32 -> LDSM ok)

struct GemmSmem {
    __nv_bfloat16 Ah[2][128][72];
    __nv_bfloat16 Al[2][128][72];
    __nv_bfloat16 Bh[2][64][72];
    __nv_bfloat16 Bl[2][64][72];
};

__global__ __launch_bounds__(256) void gemm_kernel(
    const __nv_bfloat16* __restrict__ Ahi, const __nv_bfloat16* __restrict__ Alo,
    const __nv_bfloat16* __restrict__ Bhi, const __nv_bfloat16* __restrict__ Blo,
    const float* __restrict__ bias, const float* __restrict__ R,
    void* __restrict__ Cout, __nv_bfloat16* __restrict__ Chi,
    __nv_bfloat16* __restrict__ Clo,
    int M, int N, int K, int act, int resmode, int omode)
{
    extern __shared__ char smem_raw[];
    GemmSmem* sm = (GemmSmem*)smem_raw;

    const int t    = threadIdx.x;
    const int lane = t & 31;
    const int wid  = t >> 5;
    const int wm   = wid & 3;          // row group (32 rows)
    const int wn   = wid >> 2;         // col group (32 cols)
    const int bm   = blockIdx.y << 7;
    const int bn   = blockIdx.x << 6;
    const int r    = lane >> 2;        // 0..7
    const int cq   = (lane & 3) << 1;  // 0,2,4,6

    // ldmatrix lane offsets (proven in attention kernel)
    const int g  = lane >> 3, ri = lane & 7;
    const int arow = ri + ((g & 1) << 3);   // A operand, non-trans
    const int acol = (g >> 1) << 3;
    const int vrow = ri + ((g & 1) << 3);   // B operand, trans ([k][n] layout)
    const int vcol = (g >> 1) << 3;

    float acc[2][4][4];
#pragma unroll
    for (int a = 0; a < 2; a++)
#pragma unroll
        for (int b = 0; b < 4; b++)
#pragma unroll
            for (int c = 0; c < 4; c++) acc[a][b][c] = 0.0f;

    auto stage = [&](int k0, int buf) {
#pragma unroll
        for (int i = 0; i < 4; i++) {          // A hi/lo: 128 x 64 bf16 = 1024 x16B each
            int idx = t + (i << 8);
            int row = idx >> 3, c = idx & 7;   // c in 16B (8 bf16) units
            size_t goff = (size_t)(bm + row) * K + k0 + (c << 3);
            CP_ASYNC16(smaddr(&sm->Ah[buf][row][c << 3]), Ahi + goff);
            CP_ASYNC16(smaddr(&sm->Al[buf][row][c << 3]), Alo + goff);
        }
#pragma unroll
        for (int i = 0; i < 2; i++) {          // B hi/lo: 64 x 64 bf16 = 512 x16B each
            int idx = t + (i << 8);
            int kr = idx >> 3, c = idx & 7;
            size_t goff = (size_t)(k0 + kr) * N + bn + (c << 3);
            CP_ASYNC16(smaddr(&sm->Bh[buf][kr][c << 3]), Bhi + goff);
            CP_ASYNC16(smaddr(&sm->Bl[buf][kr][c << 3]), Blo + goff);
        }
        CP_COMMIT();
    };

    stage(0, 0);
    const int NS = K >> 6;
    for (int ks = 0; ks < NS; ks++) {
        CP_WAIT0();
        __syncthreads();
        if (ks + 1 < NS) stage((ks + 1) << 6, (ks + 1) & 1);
        const int buf = ks & 1;

#pragma unroll
        for (int k16 = 0; k16 < 4; k16++) {
            int kk = k16 << 4;
            uint32_t ah[2][4], al[2][4];
#pragma unroll
            for (int mt = 0; mt < 2; mt++) {
                int rb = (wm << 5) + (mt << 4);
                LDM_X4(ah[mt][0], ah[mt][1], ah[mt][2], ah[mt][3],
                       smaddr(&sm->Ah[buf][rb + arow][kk + acol]));
                LDM_X4(al[mt][0], al[mt][1], al[mt][2], al[mt][3],
                       smaddr(&sm->Al[buf][rb + arow][kk + acol]));
            }
            uint32_t bh[2][4], bl[2][4];
#pragma unroll
            for (int nt = 0; nt < 2; nt++) {
                int cb = (wn << 5) + (nt << 4);
                LDM_X4_T(bh[nt][0], bh[nt][1], bh[nt][2], bh[nt][3],
                         smaddr(&sm->Bh[buf][kk + vrow][cb + vcol]));
                LDM_X4_T(bl[nt][0], bl[nt][1], bl[nt][2], bl[nt][3],
                         smaddr(&sm->Bl[buf][kk + vrow][cb + vcol]));
            }
#pragma unroll
            for (int mt = 0; mt < 2; mt++)
#pragma unroll
                for (int nt = 0; nt < 2; nt++)
#pragma unroll
                    for (int hf = 0; hf < 2; hf++) {
                        float* d = acc[mt][(nt << 1) + hf];
                        uint32_t b0 = bh[nt][hf << 1], b1 = bh[nt][(hf << 1) + 1];
                        mma16816(d, ah[mt][0], ah[mt][1], ah[mt][2], ah[mt][3], b0, b1);
                        mma16816(d, al[mt][0], al[mt][1], al[mt][2], al[mt][3], b0, b1);
                        mma16816(d, ah[mt][0], ah[mt][1], ah[mt][2], ah[mt][3],
                                 bl[nt][hf << 1], bl[nt][(hf << 1) + 1]);
                    }
        }
    }

    // epilogue
#pragma unroll
    for (int mt = 0; mt < 2; mt++) {
#pragma unroll
        for (int nt = 0; nt < 4; nt++) {
            int row0 = bm + (wm << 5) + (mt << 4) + r;
            int col  = bn + (wn << 5) + (nt << 3) + cq;
#pragma unroll
            for (int half = 0; half < 2; half++) {
                int row = row0 + (half << 3);
                float v0 = acc[mt][nt][half * 2 + 0] + bias[col];
                float v1 = acc[mt][nt][half * 2 + 1] + bias[col + 1];
                if (resmode == 1) {
                    const float* rr = R + (size_t)row * N + col;
                    v0 += rr[0]; v1 += rr[1];
                } else if (resmode == 2) {
                    const float* rr = R + (size_t)row * (4 * N) + col;
                    v0 += 0.25f * (rr[0] + rr[N] + rr[2 * N] + rr[3 * N]);
                    v1 += 0.25f * (rr[1] + rr[1 + N] + rr[1 + 2 * N] + rr[1 + 3 * N]);
                }
                if (act == 1) { v0 = fmaxf(v0, 0.0f); v1 = fmaxf(v1, 0.0f); }
                else if (act == 2) {
                    v0 = (v0 > 0.0f) ? v0 : expm1f(v0);
                    v1 = (v1 > 0.0f) ? v1 : expm1f(v1);
                }
                if (omode == 1) {
                    __nv_bfloat162 pk = __floats2bfloat162_rn(v0, v1);
                    *(uint32_t*)((__nv_bfloat16*)Cout + (size_t)row * N + col) =
                        *(uint32_t*)&pk;
                } else {
                    *(float2*)((float*)Cout + (size_t)row * N + col) =
                        make_float2(v0, v1);
                    __nv_bfloat16 h0, h1, l0, l1;
                    bf16split(v0, h0, l0);
                    bf16split(v1, h1, l1);
                    __nv_bfloat162 ph = {h0, h1}, pl = {l0, l1};
                    *(uint32_t*)(Chi + (size_t)row * N + col) = *(uint32_t*)&ph;
                    *(uint32_t*)(Clo + (size_t)row * N + col) = *(uint32_t*)&pl;
                }
            }
        }
    }
}

// ---------------- LayerNorm: warp per row, 8 rows/block; writes fp32 + hi/lo ----------------
__global__ __launch_bounds__(256) void ln_kernel(
    const float* __restrict__ X, const float* __restrict__ gw,
    const float* __restrict__ bw, float* __restrict__ Y,
    __nv_bfloat16* __restrict__ Yhi, __nv_bfloat16* __restrict__ Ylo)
{
    const int row  = (blockIdx.x << 3) + (threadIdx.x >> 5);
    const int lane = threadIdx.x & 31;
    const float4* xr = (const float4*)(X + (size_t)row * DD);
    float4 a = xr[lane];
    float4 b = xr[lane + 32];
    float sum = a.x + a.y + a.z + a.w + b.x + b.y + b.z + b.w;
#pragma unroll
    for (int o = 16; o > 0; o >>= 1)
        sum += __shfl_xor_sync(0xffffffffu, sum, o);
    float mean = sum * (1.0f / DD);
    float dax = a.x - mean, day = a.y - mean, daz = a.z - mean, daw = a.w - mean;
    float dbx = b.x - mean, dby = b.y - mean, dbz = b.z - mean, dbw = b.w - mean;
    float vs = dax * dax + day * day + daz * daz + daw * daw +
               dbx * dbx + dby * dby + dbz * dbz + dbw * dbw;
#pragma unroll
    for (int o = 16; o > 0; o >>= 1)
        vs += __shfl_xor_sync(0xffffffffu, vs, o);
    float inv = rsqrtf(vs * (1.0f / DD) + 1e-5f);
    float4 g0 = ((const float4*)gw)[lane];
    float4 g1 = ((const float4*)gw)[lane + 32];
    float4 b0 = ((const float4*)bw)[lane];
    float4 b1 = ((const float4*)bw)[lane + 32];
    float4 o0 = make_float4(dax * inv * g0.x + b0.x, day * inv * g0.y + b0.y,
                            daz * inv * g0.z + b0.z, daw * inv * g0.w + b0.w);
    float4 o1 = make_float4(dbx * inv * g1.x + b1.x, dby * inv * g1.y + b1.y,
                            dbz * inv * g1.z + b1.z, dbw * inv * g1.w + b1.w);
    float4* yr = (float4*)(Y + (size_t)row * DD);
    yr[lane] = o0;
    yr[lane + 32] = o1;

    __nv_bfloat16 h0, h1, h2, h3, l0, l1, l2, l3;
    size_t base = (size_t)row * DD;
    bf16split(o0.x, h0, l0); bf16split(o0.y, h1, l1);
    bf16split(o0.z, h2, l2); bf16split(o0.w, h3, l3);
    {
        __nv_bfloat162 ph0 = {h0, h1}, ph1 = {h2, h3};
        __nv_bfloat162 pl0 = {l0, l1}, pl1 = {l2, l3};
        *(__nv_bfloat162*)(Yhi + base + (lane << 2))     = ph0;
        *(__nv_bfloat162*)(Yhi + base + (lane << 2) + 2) = ph1;
        *(__nv_bfloat162*)(Ylo + base + (lane << 2))     = pl0;
        *(__nv_bfloat162*)(Ylo + base + (lane << 2) + 2) = pl1;
    }
    bf16split(o1.x, h0, l0); bf16split(o1.y, h1, l1);
    bf16split(o1.z, h2, l2); bf16split(o1.w, h3, l3);
    {
        __nv_bfloat162 ph0 = {h0, h1}, ph1 = {h2, h3};
        __nv_bfloat162 pl0 = {l0, l1}, pl1 = {l2, l3};
        *(__nv_bfloat162*)(Yhi + base + 128 + (lane << 2))     = ph0;
        *(__nv_bfloat162*)(Yhi + base + 128 + (lane << 2) + 2) = ph1;
        *(__nv_bfloat162*)(Ylo + base + 128 + (lane << 2))     = pl0;
        *(__nv_bfloat162*)(Ylo + base + 128 + (lane << 2) + 2) = pl1;
    }
}

// ===================== flash attention (unchanged, 508us version) =====================
// Br=128, Bc=64, DH=256: grid (32,4) = 128 blocks = ONE wave on 148 SMs.

#define BR 128
#define BC 64

struct AttnSmem {
    __nv_bfloat16 Qs[BR][264];
    __nv_bfloat16 Ks[2][BC][264];
    __nv_bfloat16 Vs[2][BC][264];
    __nv_bfloat16 Pb[BR][72];
    float l_part[2][BR];
};

__global__ __launch_bounds__(512) void attn_kernel(
    const __nv_bfloat16* __restrict__ Qg, const __nv_bfloat16* __restrict__ Kg,
    const __nv_bfloat16* __restrict__ Vg, float* __restrict__ O)
{
    extern __shared__ char smem_raw[];
    AttnSmem* s = (AttnSmem*)smem_raw;

    const int t    = threadIdx.x;
    const int wid  = t >> 5;
    const int lane = t & 31;
    const int h    = blockIdx.y;
    const int q0   = blockIdx.x * BR;
    const int hoff = h * 256;

    const int r  = lane >> 2;
    const int cq = (lane & 3) << 1;

    const int wm = wid & 7;
    const int wn = wid >> 3;
    const int sm_row = wm << 4;

    const int g  = lane >> 3, ri = lane & 7;
    const int arow = ri + ((g & 1) << 3);
    const int acol = (g >> 1) << 3;
    const int brow = ri + ((g >> 1) << 3);
    const int bcol = (g & 1) << 3;
    const int vrow = ri + ((g & 1) << 3);
    const int vcol = (g >> 1) << 3;

    for (int i = t; i < BR * 32; i += 512) {
        int rr = i >> 5, c4 = i & 31;
        *(float4*)&s->Qs[rr][c4 << 3] =
            ((const float4*)(Qg + (size_t)(q0 + rr) * HD + hoff))[c4];
    }

    float oacc[16][4];
#pragma unroll
    for (int a = 0; a < 16; a++)
#pragma unroll
        for (int b = 0; b < 4; b++) oacc[a][b] = 0.0f;
    float lA = 0.0f, lB = 0.0f;

    auto stage = [&](int kb, int buf) {
#pragma unroll
        for (int i = 0; i < 4; i++) {
            int idx = t + (i << 9);
            int row = idx >> 5, c = idx & 31;
            CP_ASYNC16(smaddr(&s->Ks[buf][row][c << 3]),
                       Kg + (size_t)(kb + row) * HD + hoff + (c << 3));
        }
#pragma unroll
        for (int i = 0; i < 4; i++) {
            int idx = t + (i << 9);
            int row = idx >> 5, c = idx & 31;
            CP_ASYNC16(smaddr(&s->Vs[buf][row][c << 3]),
                       Vg + (size_t)(kb + row) * HD + hoff + (c << 3));
        }
        CP_COMMIT();
    };

    stage(0, 0);
    const int NIT = NN / BC;
    for (int ib = 0; ib < NIT; ib++) {
        CP_WAIT0();
        __syncthreads();
        if (ib + 1 < NIT) stage((ib + 1) * BC, (ib + 1) & 1);
        const int cur = ib & 1;

        {
            const int sn = wn << 5;
            float sacc[4][4] = {};
#pragma unroll 4
            for (int k0 = 0; k0 < 256; k0 += 16) {
                uint32_t a0, a1, a2, a3, b0, b1, b2, b3, b4, b5, b6, b7;
                LDM_X4(a0, a1, a2, a3, smaddr(&s->Qs[sm_row + arow][k0 + acol]));
                LDM_X4(b0, b1, b2, b3, smaddr(&s->Ks[cur][sn + brow][k0 + bcol]));
                LDM_X4(b4, b5, b6, b7, smaddr(&s->Ks[cur][sn + 16 + brow][k0 + bcol]));
                mma16816(sacc[0], a0, a1, a2, a3, b0, b1);
                mma16816(sacc[1], a0, a1, a2, a3, b2, b3);
                mma16816(sacc[2], a0, a1, a2, a3, b4, b5);
                mma16816(sacc[3], a0, a1, a2, a3, b6, b7);
            }
            const float sc = 0.0625f;
#pragma unroll
            for (int nt = 0; nt < 4; nt++) {
                int col = sn + (nt << 3) + cq;
                float p0 = __expf(sacc[nt][0] * sc);
                float p1 = __expf(sacc[nt][1] * sc);
                float p2 = __expf(sacc[nt][2] * sc);
                float p3 = __expf(sacc[nt][3] * sc);
                lA += p0 + p1;
                lB += p2 + p3;
                __nv_bfloat162 pa = __floats2bfloat162_rn(p0, p1);
                __nv_bfloat162 pb = __floats2bfloat162_rn(p2, p3);
                *(uint32_t*)&s->Pb[sm_row + r][col]     = *(uint32_t*)&pa;
                *(uint32_t*)&s->Pb[sm_row + 8 + r][col] = *(uint32_t*)&pb;
            }
        }
        __syncthreads();

        {
            const int dn = wn << 7;
#pragma unroll
            for (int k0 = 0; k0 < BC; k0 += 16) {
                uint32_t p0, p1, p2, p3;
                LDM_X4(p0, p1, p2, p3, smaddr(&s->Pb[sm_row + arow][k0 + acol]));
#pragma unroll
                for (int nt2 = 0; nt2 < 8; nt2++) {
                    uint32_t v0, v1, v2, v3;
                    LDM_X4_T(v0, v1, v2, v3,
                             smaddr(&s->Vs[cur][k0 + vrow][dn + (nt2 << 4) + vcol]));
                    mma16816(oacc[nt2 * 2],     p0, p1, p2, p3, v0, v1);
                    mma16816(oacc[nt2 * 2 + 1], p0, p1, p2, p3, v2, v3);
                }
            }
        }
    }

    lA += __shfl_xor_sync(0xffffffffu, lA, 1);
    lA += __shfl_xor_sync(0xffffffffu, lA, 2);
    lB += __shfl_xor_sync(0xffffffffu, lB, 1);
    lB += __shfl_xor_sync(0xffffffffu, lB, 2);
    if ((lane & 3) == 0) {
        s->l_part[wn][sm_row + r] = lA;
        s->l_part[wn][sm_row + 8 + r] = lB;
    }
    __syncthreads();

    {
        const int dn = wn << 7;
        int rowA = sm_row + r, rowB = sm_row + 8 + r;
        float la = s->l_part[0][rowA] + s->l_part[1][rowA];
        float lb = s->l_part[0][rowB] + s->l_part[1][rowB];
        float ia = 1.0f / la;
        float ib2 = 1.0f / lb;
#pragma unroll
        for (int nt = 0; nt < 16; nt++) {
            int col = dn + (nt << 3) + cq;
            float2 va = make_float2(oacc[nt][0] * ia,  oacc[nt][1] * ia);
            float2 vb = make_float2(oacc[nt][2] * ib2, oacc[nt][3] * ib2);
            *(float2*)&O[(size_t)(q0 + rowA) * HD + hoff + col] = va;
            *(float2*)&O[(size_t)(q0 + rowB) * HD + hoff + col] = vb;
        }
    }
}

// ---------------- launch ----------------
extern "C" void kernel_launch(void* const* d_in, const int* in_sizes, int n_in,
                              void* d_out, int out_size)
{
    const float* x     = (const float*)d_in[0];
    const float* w_in  = (const float*)d_in[1];
    const float* b_in  = (const float*)d_in[2];
    const float* w_m1  = (const float*)d_in[3];
    const float* b_m1  = (const float*)d_in[4];
    const float* gm1   = (const float*)d_in[5];
    const float* bem1  = (const float*)d_in[6];
    const float* wq    = (const float*)d_in[7];
    const float* bq    = (const float*)d_in[8];
    const float* wk    = (const float*)d_in[9];
    const float* bk    = (const float*)d_in[10];
    const float* wv    = (const float*)d_in[11];
    const float* bv    = (const float*)d_in[12];
    const float* wskip = (const float*)d_in[13];
    const float* bskip = (const float*)d_in[14];
    const float* gn1   = (const float*)d_in[15];
    const float* ben1  = (const float*)d_in[16];
    const float* w_m2  = (const float*)d_in[17];
    const float* b_m2  = (const float*)d_in[18];
    const float* gm2   = (const float*)d_in[19];
    const float* bem2  = (const float*)d_in[20];
    const float* w_mean = (const float*)d_in[21];
    const float* b_mean = (const float*)d_in[22];
    float* out = (float*)d_out;

    float *t1, *t2, *h, *o;
    __nv_bfloat16 *qb, *kb, *vb, *hiA, *loA, *hiB, *loB, *whi, *wlo;
    cudaGetSymbolAddress((void**)&t1, g_t1);
    cudaGetSymbolAddress((void**)&t2, g_t2);
    cudaGetSymbolAddress((void**)&h,  g_h);
    cudaGetSymbolAddress((void**)&qb, g_qb);
    cudaGetSymbolAddress((void**)&kb, g_kb);
    cudaGetSymbolAddress((void**)&vb, g_vb);
    cudaGetSymbolAddress((void**)&o,  g_o);
    cudaGetSymbolAddress((void**)&hiA, g_hiA);
    cudaGetSymbolAddress((void**)&loA, g_loA);
    cudaGetSymbolAddress((void**)&hiB, g_hiB);
    cudaGetSymbolAddress((void**)&loB, g_loB);
    cudaGetSymbolAddress((void**)&whi, g_whi);
    cudaGetSymbolAddress((void**)&wlo, g_wlo);

    const int ATTN_SMEM = (int)sizeof(AttnSmem);
    const int GEMM_SMEM = (int)sizeof(GemmSmem);
    cudaFuncSetAttribute(attn_kernel, cudaFuncAttributeMaxDynamicSharedMemorySize,
                         ATTN_SMEM);
    cudaFuncSetAttribute(gemm_kernel, cudaFuncAttributeMaxDynamicSharedMemorySize,
                         GEMM_SMEM);

    // split weights (bf16 hi/lo) + x
    SplitArgs sa;
    sa.src[0] = w_in;   sa.off[0] = OFF_WIN;   sa.n[0] = DD * DD;
    sa.src[1] = w_m1;   sa.off[1] = OFF_WM1;   sa.n[1] = DD * DD;
    sa.src[2] = wskip;  sa.off[2] = OFF_WSKIP; sa.n[2] = DD * DD;
    sa.src[3] = w_m2;   sa.off[3] = OFF_WM2;   sa.n[3] = DD * DD;
    sa.src[4] = w_mean; sa.off[4] = OFF_WMEAN; sa.n[4] = DD * OUTD;
    sa.src[5] = wq;     sa.off[5] = OFF_WQ;    sa.n[5] = DD * HD;
    sa.src[6] = wk;     sa.off[6] = OFF_WK;    sa.n[6] = DD * HD;
    sa.src[7] = wv;     sa.off[7] = OFF_WV;    sa.n[7] = DD * HD;
    wsplit_kernel<<<dim3(64, 8), 256>>>(sa, whi, wlo);
    xsplit_kernel<<<NN * DD / 4 / 256, 256>>>(x, hiA, loA);

    dim3 blk(256);
    dim3 gD(DD / 64, NN / 128);
    dim3 gH(HD / 64, NN / 128);
    dim3 gO(OUTD / 64, NN / 128);
    dim3 gLN(NN / 8);

    // input_layer: t1 = elu(x @ w_in + b_in + x)   [hilo -> B]
    gemm_kernel<<<gD, blk, GEMM_SMEM>>>(hiA, loA, whi + OFF_WIN, wlo + OFF_WIN,
                                        b_in, x, t1, hiB, loB, NN, DD, DD, 2, 1, 0);
    // mlp1 pre-LN: t2 = relu(t1 @ w_m1 + b_m1 + t1)   [hilo -> A, unused]
    gemm_kernel<<<gD, blk, GEMM_SMEM>>>(hiB, loB, whi + OFF_WM1, wlo + OFF_WM1,
                                        b_m1, t1, t2, hiA, loA, NN, DD, DD, 1, 1, 0);
    ln_kernel<<<gLN, blk>>>(t2, gm1, bem1, h, hiB, loB);
    // QKV -> bf16
    gemm_kernel<<<gH, blk, GEMM_SMEM>>>(hiB, loB, whi + OFF_WQ, wlo + OFF_WQ,
                                        bq, nullptr, qb, nullptr, nullptr,
                                        NN, HD, DD, 0, 0, 1);
    gemm_kernel<<<gH, blk, GEMM_SMEM>>>(hiB, loB, whi + OFF_WK, wlo + OFF_WK,
                                        bk, nullptr, kb, nullptr, nullptr,
                                        NN, HD, DD, 0, 0, 1);
    gemm_kernel<<<gH, blk, GEMM_SMEM>>>(hiB, loB, whi + OFF_WV, wlo + OFF_WV,
                                        bv, nullptr, vb, nullptr, nullptr,
                                        NN, HD, DD, 0, 0, 1);
    // attention
    attn_kernel<<<dim3(NN / BR, HH), dim3(512), ATTN_SMEM>>>(qb, kb, vb, o);
    // skip: t1 = head_mean(O) + h @ wskip + bskip   [hilo -> A, unused]
    gemm_kernel<<<gD, blk, GEMM_SMEM>>>(hiB, loB, whi + OFF_WSKIP, wlo + OFF_WSKIP,
                                        bskip, o, t1, hiA, loA, NN, DD, DD, 0, 2, 0);
    ln_kernel<<<gLN, blk>>>(t1, gn1, ben1, t2, hiA, loA);
    // mlp2: t1 = relu(t2 @ w_m2 + b_m2 + t2)   [hilo -> B, unused]
    gemm_kernel<<<gD, blk, GEMM_SMEM>>>(hiA, loA, whi + OFF_WM2, wlo + OFF_WM2,
                                        b_m2, t2, t1, hiB, loB, NN, DD, DD, 1, 1, 0);
    ln_kernel<<<gLN, blk>>>(t1, gm2, bem2, h, hiA, loA);
    // output head
    gemm_kernel<<<gO, blk, GEMM_SMEM>>>(hiA, loA, whi + OFF_WMEAN, wlo + OFF_WMEAN,
                                        b_mean, nullptr, out, hiB, loB,
                                        NN, OUTD, DD, 0, 0, 0);
}